// round 12
// baseline (speedup 1.0000x reference)
#include <cuda_runtime.h>
#include <cuda_bf16.h>
#include <cstdint>
#include <math.h>

// Problem constants
#define Bv   4
#define Cv   256
#define Hv   64
#define Wv   64
#define HW   4096          // Hv*Wv
#define NPIX 16384         // Bv*HW
#define NEL  4194304u      // Bv*Cv*HW
#define NHEAD 8
#define DHEAD 32
#define WELEM 65536        // 256*256 weight matrix elems
#define NWMAT 10

// Scratch: 16 fp32 tensors + pre-rounded weights (~271 MB).
__device__ float g_scratch[16u * NEL + NWMAT * WELEM];

// ---------------------------------------------------------------------------
// PTX helpers
// ---------------------------------------------------------------------------
__device__ __forceinline__ void cp_async16(void* smem_dst, const void* gsrc) {
    uint32_t s = (uint32_t)__cvta_generic_to_shared(smem_dst);
    asm volatile("cp.async.ca.shared.global [%0], [%1], 16;\n" :: "r"(s), "l"(gsrc));
}
__device__ __forceinline__ void cp_commit() {
    asm volatile("cp.async.commit_group;\n");
}
__device__ __forceinline__ void cp_wait0() {
    asm volatile("cp.async.wait_group 0;\n");
}
__device__ __forceinline__ uint32_t f2tf32(float x) {
    uint32_t y;
    asm("cvt.rna.tf32.f32 %0, %1;" : "=r"(y) : "f"(x));
    return y;
}
__device__ __forceinline__ void mma_tf32(float* d, const uint32_t* a, const uint32_t* b) {
    asm volatile(
        "mma.sync.aligned.m16n8k8.row.col.f32.tf32.tf32.f32 "
        "{%0,%1,%2,%3}, {%4,%5,%6,%7}, {%8,%9}, {%0,%1,%2,%3};\n"
        : "+f"(d[0]), "+f"(d[1]), "+f"(d[2]), "+f"(d[3])
        : "r"(a[0]), "r"(a[1]), "r"(a[2]), "r"(a[3]), "r"(b[0]), "r"(b[1]));
}

// ---------------------------------------------------------------------------
// Pre-round 10 weight matrices to tf32 (RNA) once.
// ---------------------------------------------------------------------------
struct WPtrs { const float* p[NWMAT]; };

__global__ void round_weights_kernel(WPtrs wp, float* __restrict__ dst) {
    int m = blockIdx.y;
    int i = blockIdx.x * blockDim.x + threadIdx.x;
    dst[m * WELEM + i] = __uint_as_float(f2tf32(wp.p[m][i]));
}

// ---------------------------------------------------------------------------
// conv1x1 as tf32 tensor-core GEMM, z-batched over two chains, y-split over
// two weight/input groups (primary rows [0, ysplit*128), secondary above).
// X channel-plane; output either channel-plane (PIX=0) or pixel-major
// [b,head,pixel,d] (PIX=1) for attention consumption. Stacked-M segments.
// BM=128, BN=256, BK=32, 256 threads, warp tile 64x64.
// ---------------------------------------------------------------------------
#define BK     32
#define A_STR  36
#define B_STR  264
#define A_SZ   (128 * A_STR)
#define B_SZ   (BK * B_STR)
#define STG    (A_SZ + B_SZ)
#define SMEM_BYTES (2 * STG * 4)       // 104448 B

template<bool RELU, bool BIAS, bool PIX>
__global__ __launch_bounds__(256, 1)
void conv1x1_tc_kernel(const float* __restrict__ Xp0, const float* __restrict__ Xp1,
                       const float* __restrict__ Xs0, const float* __restrict__ Xs1,
                       const float* __restrict__ Wm,
                       const float* __restrict__ bias,
                       float* __restrict__ Yp0, float* __restrict__ Yp1,
                       float* __restrict__ Ys0, float* __restrict__ Ys1,
                       int ysplit)
{
    extern __shared__ float smem[];

    const bool sec = (int)blockIdx.y >= ysplit;
    const float* X = sec ? (blockIdx.z ? Xs1 : Xs0) : (blockIdx.z ? Xp1 : Xp0);
    float*       Y = sec ? (blockIdx.z ? Ys1 : Ys0) : (blockIdx.z ? Yp1 : Yp0);

    const int tb_n = blockIdx.x * 256;
    const int tb_m = blockIdx.y * 128;              // row into stacked weights
    const int row0 = sec ? tb_m - ysplit * 128 : tb_m;  // row into output stack
    const int b    = tb_n >> 12;
    const int p0   = tb_n & 4095;

    const int t    = threadIdx.x;
    const int lane = t & 31;
    const int warp = t >> 5;
    const int wm0  = (warp >> 2) * 64;
    const int wn0  = (warp & 3) * 64;

    const float* Xbase = X + ((size_t)(b * Cv) << 12) + p0;

    float acc[4][8][4];
    #pragma unroll
    for (int i = 0; i < 4; i++)
        #pragma unroll
        for (int j = 0; j < 8; j++)
            #pragma unroll
            for (int r = 0; r < 4; r++) acc[i][j][r] = 0.0f;

    auto load_tile = [&](int kt, int s) {
        float* As = smem + s * STG;
        float* Bs = As + A_SZ;
        int k0 = kt * BK;
        #pragma unroll
        for (int i = 0; i < 4; i++) {
            int id = t + i * 256;
            int m  = id >> 3;
            int kq = id & 7;
            cp_async16(&As[m * A_STR + kq * 4],
                       Wm + (size_t)(tb_m + m) * Cv + k0 + kq * 4);
        }
        #pragma unroll
        for (int i = 0; i < 8; i++) {
            int id = t + i * 256;
            int kk = id >> 6;
            int nq = id & 63;
            cp_async16(&Bs[kk * B_STR + nq * 4],
                       Xbase + ((size_t)(k0 + kk) << 12) + nq * 4);
        }
        cp_commit();
    };

    load_tile(0, 0);

    const int a_r = lane >> 2;
    const int a_c = lane & 3;

    int buf = 0;
    const int KT = Cv / BK;
    for (int kt = 0; kt < KT; kt++) {
        cp_wait0();
        __syncthreads();
        if (kt + 1 < KT) load_tile(kt + 1, buf ^ 1);

        const float* As = smem + buf * STG;
        const float* Bs = As + A_SZ;

        #pragma unroll
        for (int ks = 0; ks < 4; ks++) {
            int kb = ks * 8;
            uint32_t afr[4][4], bfr[8][2];
            #pragma unroll
            for (int mi = 0; mi < 4; mi++) {
                const float* ap = As + (wm0 + mi * 16 + a_r) * A_STR + kb + a_c;
                afr[mi][0] = __float_as_uint(ap[0]);
                afr[mi][1] = __float_as_uint(ap[8 * A_STR]);
                afr[mi][2] = __float_as_uint(ap[4]);
                afr[mi][3] = __float_as_uint(ap[8 * A_STR + 4]);
            }
            #pragma unroll
            for (int ni = 0; ni < 8; ni++) {
                const float* bp = Bs + (kb + a_c) * B_STR + wn0 + ni * 8 + a_r;
                bfr[ni][0] = f2tf32(bp[0]);
                bfr[ni][1] = f2tf32(bp[4 * B_STR]);
            }
            #pragma unroll
            for (int mi = 0; mi < 4; mi++)
                #pragma unroll
                for (int ni = 0; ni < 8; ni++)
                    mma_tf32(acc[mi][ni], afr[mi], bfr[ni]);
        }
        __syncthreads();
        buf ^= 1;
    }

    #pragma unroll
    for (int mi = 0; mi < 4; mi++) {
        int rg  = row0 + wm0 + mi * 16 + a_r;
        int seg = rg >> 8;
        int ch  = rg & 255;
        float bv0 = BIAS ? bias[ch]     : 0.0f;
        float bv1 = BIAS ? bias[ch + 8] : 0.0f;
        if (PIX) {
            // pixel-major: [b*8+h][pixel][d]; ch%32<=23 so ch and ch+8 share h.
            int h  = ch >> 5;
            int d0 = ch & 31;
            float* basep = Y + (size_t)seg * NEL
                         + ((size_t)(b * NHEAD + h) << 17) + d0;
            #pragma unroll
            for (int ni = 0; ni < 8; ni++) {
                int cb = p0 + wn0 + ni * 8 + 2 * a_c;
                float* q0 = basep + ((size_t)cb << 5);
                q0[0]      = acc[mi][ni][0];
                q0[8]      = acc[mi][ni][2];
                q0[32]     = acc[mi][ni][1];
                q0[40]     = acc[mi][ni][3];
            }
        } else {
            float* Ys = Y + (size_t)seg * NEL;
            #pragma unroll
            for (int ni = 0; ni < 8; ni++) {
                int cb = p0 + wn0 + ni * 8 + 2 * a_c;
                size_t off0 = ((size_t)(b * Cv + ch) << 12) + cb;
                size_t off1 = off0 + ((size_t)8 << 12);
                float v0 = acc[mi][ni][0] + bv0;
                float v1 = acc[mi][ni][1] + bv0;
                float v2 = acc[mi][ni][2] + bv1;
                float v3 = acc[mi][ni][3] + bv1;
                if (RELU) {
                    v0 = fmaxf(v0, 0.0f); v1 = fmaxf(v1, 0.0f);
                    v2 = fmaxf(v2, 0.0f); v3 = fmaxf(v3, 0.0f);
                }
                *(float2*)(Ys + off0) = make_float2(v0, v1);
                *(float2*)(Ys + off1) = make_float2(v2, v3);
            }
        }
    }
}

// ---------------------------------------------------------------------------
// Fused fc conv + residual + LayerNorm, z-batched.
// B operand = attn output in PIXEL-MAJOR layout; K-tile == one head (k=h*32+d),
// so each B tile row is 128B contiguous. Bt smem [128 px][36] (transposed use).
// A = fc weights channel-plane. Output channel-plane fp32.
// ---------------------------------------------------------------------------
#define LA_STR 36
#define LA_SZ  (256 * LA_STR)          // 9216 floats
#define LBT_STR 36
#define LBT_SZ (128 * LBT_STR)         // 4608 floats
#define LSTG   (LA_SZ + LBT_SZ)        // 13824 floats
#define S_STR  257
#define LSMEM_BYTES (128 * S_STR * 4)  // 131584 >= 2*LSTG*4=110592

__global__ __launch_bounds__(256, 1)
void convln_kernel(const float* __restrict__ X0, const float* __restrict__ X1,
                   const float* __restrict__ Wm,
                   const float* __restrict__ res0, const float* __restrict__ res1,
                   const float* __restrict__ g,
                   const float* __restrict__ bt,
                   float* __restrict__ Y0, float* __restrict__ Y1)
{
    extern __shared__ float smem[];
    __shared__ float red[2][2][128];
    __shared__ float mus[128], rss[128];

    const float* X   = blockIdx.y ? X1   : X0;   // pixel-major attn output
    const float* res = blockIdx.y ? res1 : res0;
    float*       Y   = blockIdx.y ? Y1   : Y0;

    const int tb_n = blockIdx.x * 128;
    const int b    = tb_n >> 12;
    const int p0   = tb_n & 4095;

    const int t    = threadIdx.x;
    const int lane = t & 31;
    const int warp = t >> 5;
    const int wm0  = (warp >> 1) * 64;
    const int wn0  = (warp & 1) * 64;

    float acc[4][8][4];
    #pragma unroll
    for (int i = 0; i < 4; i++)
        #pragma unroll
        for (int j = 0; j < 8; j++)
            #pragma unroll
            for (int r = 0; r < 4; r++) acc[i][j][r] = 0.0f;

    auto load_tile = [&](int kt, int s) {     // kt == head index
        float* As = smem + s * LSTG;
        float* Bt = As + LA_SZ;
        int k0 = kt * BK;
        #pragma unroll
        for (int i = 0; i < 8; i++) {
            int id = t + i * 256;
            int m  = id >> 3;
            int kq = id & 7;
            cp_async16(&As[m * LA_STR + kq * 4],
                       Wm + (size_t)m * Cv + k0 + kq * 4);
        }
        const float* Xh = X + ((size_t)(b * NHEAD + kt) << 17) + ((size_t)p0 << 5);
        #pragma unroll
        for (int i = 0; i < 4; i++) {
            int id = t + i * 256;              // 0..1023
            int p  = id >> 3;                  // 0..127
            int q  = id & 7;
            cp_async16(&Bt[p * LBT_STR + q * 4],
                       Xh + ((size_t)p << 5) + q * 4);
        }
        cp_commit();
    };

    load_tile(0, 0);

    const int a_r = lane >> 2;
    const int a_c = lane & 3;

    int buf = 0;
    for (int kt = 0; kt < 8; kt++) {
        cp_wait0();
        __syncthreads();
        if (kt + 1 < 8) load_tile(kt + 1, buf ^ 1);

        const float* As = smem + buf * LSTG;
        const float* Bt = As + LA_SZ;

        #pragma unroll
        for (int ks = 0; ks < 4; ks++) {
            int kb = ks * 8;
            uint32_t afr[4][4], bfr[8][2];
            #pragma unroll
            for (int mi = 0; mi < 4; mi++) {
                const float* ap = As + (wm0 + mi * 16 + a_r) * LA_STR + kb + a_c;
                afr[mi][0] = __float_as_uint(ap[0]);
                afr[mi][1] = __float_as_uint(ap[8 * LA_STR]);
                afr[mi][2] = __float_as_uint(ap[4]);
                afr[mi][3] = __float_as_uint(ap[8 * LA_STR + 4]);
            }
            #pragma unroll
            for (int ni = 0; ni < 8; ni++) {
                const float* bp = Bt + (wn0 + ni * 8 + a_r) * LBT_STR + kb + a_c;
                bfr[ni][0] = f2tf32(bp[0]);
                bfr[ni][1] = f2tf32(bp[4]);
            }
            #pragma unroll
            for (int mi = 0; mi < 4; mi++)
                #pragma unroll
                for (int ni = 0; ni < 8; ni++)
                    mma_tf32(acc[mi][ni], afr[mi], bfr[ni]);
        }
        __syncthreads();
        buf ^= 1;
    }

    // Phase 1: fragments + residual -> S[pixel][channel]
    float* S = smem;
    #pragma unroll
    for (int mi = 0; mi < 4; mi++) {
        int rbase = wm0 + mi * 16 + a_r;
        #pragma unroll
        for (int ni = 0; ni < 8; ni++) {
            int cbase = wn0 + ni * 8 + 2 * a_c;
            size_t off0 = ((size_t)(b * Cv + rbase) << 12) + p0 + cbase;
            size_t off1 = off0 + ((size_t)8 << 12);
            float2 r0 = *(const float2*)(res + off0);
            float2 r1 = *(const float2*)(res + off1);
            S[cbase * S_STR + rbase]           = acc[mi][ni][0] + r0.x;
            S[(cbase + 1) * S_STR + rbase]     = acc[mi][ni][1] + r0.y;
            S[cbase * S_STR + rbase + 8]       = acc[mi][ni][2] + r1.x;
            S[(cbase + 1) * S_STR + rbase + 8] = acc[mi][ni][3] + r1.y;
        }
    }
    __syncthreads();

    // Phase 2: per-pixel mean/var.
    {
        int p = t & 127, q = t >> 7;
        float s = 0.0f, s2 = 0.0f;
        const float* row = S + p * S_STR + q * 128;
        #pragma unroll 8
        for (int j = 0; j < 128; j++) { float v = row[j]; s += v; s2 += v * v; }
        red[0][q][p] = s; red[1][q][p] = s2;
    }
    __syncthreads();
    if (t < 128) {
        float s  = red[0][0][t] + red[0][1][t];
        float s2 = red[1][0][t] + red[1][1][t];
        float mu  = s * (1.0f / Cv);
        float var = s2 * (1.0f / Cv) - mu * mu;
        mus[t] = mu;
        rss[t] = rsqrtf(var + 1e-6f);
    }
    __syncthreads();

    // Phase 3: normalize + write.
    {
        int p = t & 127;
        float mu = mus[p], rstd = rss[p];
        int c0 = t >> 7;
        #pragma unroll 4
        for (int i = 0; i < 128; i++) {
            int c = c0 + 2 * i;
            float v = S[p * S_STR + c];
            Y[((size_t)(b * Cv + c) << 12) + p0 + p] =
                (v - mu) * rstd * g[c] + bt[c];
        }
    }
}

// ---------------------------------------------------------------------------
// Local 3x3 windowed attention, one thread per (b, head, pixel), z-batched.
// Q/K/V/O in PIXEL-MAJOR layout -> all float4 loads/stores.
// ---------------------------------------------------------------------------
__global__ void local_attn_kernel(const float* __restrict__ Q0, const float* __restrict__ K0,
                                  const float* __restrict__ V0, float* __restrict__ O0,
                                  const float* __restrict__ Q1, const float* __restrict__ K1,
                                  const float* __restrict__ V1, float* __restrict__ O1)
{
    const float* Q = blockIdx.y ? Q1 : Q0;
    const float* K = blockIdx.y ? K1 : K0;
    const float* V = blockIdx.y ? V1 : V0;
    float*       O = blockIdx.y ? O1 : O0;

    int n = blockIdx.x * blockDim.x + threadIdx.x;   // 0 .. 131071
    int p    = n & 4095;
    int x    = p & 63;
    int y    = p >> 6;
    int head = (n >> 12) & 7;
    int b    = n >> 15;

    size_t base = (size_t)((n >> 12)) << 17;         // (b*8+head) plane

    float q[DHEAD];
    {
        const float4* qp = (const float4*)(Q + base + ((size_t)p << 5));
        #pragma unroll
        for (int i = 0; i < 8; i++) {
            float4 v = qp[i];
            q[4 * i] = v.x; q[4 * i + 1] = v.y; q[4 * i + 2] = v.z; q[4 * i + 3] = v.w;
        }
    }

    const float scale = 0.17677669529663687f; // 1/sqrt(32)

    float logits[9];
    #pragma unroll
    for (int ki = 0; ki < 3; ki++) {
        #pragma unroll
        for (int kj = 0; kj < 3; kj++) {
            int yy = y + ki - 1, xx = x + kj - 1;
            float acc = 0.0f;
            if (yy >= 0 && yy < Hv && xx >= 0 && xx < Wv) {
                const float4* kp = (const float4*)(K + base + ((size_t)(yy * Wv + xx) << 5));
                #pragma unroll
                for (int i = 0; i < 8; i++) {
                    float4 v = kp[i];
                    acc = fmaf(q[4 * i],     v.x, acc);
                    acc = fmaf(q[4 * i + 1], v.y, acc);
                    acc = fmaf(q[4 * i + 2], v.z, acc);
                    acc = fmaf(q[4 * i + 3], v.w, acc);
                }
                acc *= scale;
            }
            logits[ki * 3 + kj] = acc;
        }
    }

    float m = logits[0];
    #pragma unroll
    for (int i = 1; i < 9; i++) m = fmaxf(m, logits[i]);
    float wgt[9]; float s = 0.0f;
    #pragma unroll
    for (int i = 0; i < 9; i++) { wgt[i] = __expf(logits[i] - m); s += wgt[i]; }
    float inv = 1.0f / s;
    #pragma unroll
    for (int i = 0; i < 9; i++) wgt[i] *= inv;

    float o[DHEAD];
    #pragma unroll
    for (int d = 0; d < DHEAD; d++) o[d] = 0.0f;
    #pragma unroll
    for (int ki = 0; ki < 3; ki++) {
        #pragma unroll
        for (int kj = 0; kj < 3; kj++) {
            int yy = y + ki - 1, xx = x + kj - 1;
            if (yy >= 0 && yy < Hv && xx >= 0 && xx < Wv) {
                float w = wgt[ki * 3 + kj];
                const float4* vp = (const float4*)(V + base + ((size_t)(yy * Wv + xx) << 5));
                #pragma unroll
                for (int i = 0; i < 8; i++) {
                    float4 v = vp[i];
                    o[4 * i]     = fmaf(w, v.x, o[4 * i]);
                    o[4 * i + 1] = fmaf(w, v.y, o[4 * i + 1]);
                    o[4 * i + 2] = fmaf(w, v.z, o[4 * i + 2]);
                    o[4 * i + 3] = fmaf(w, v.w, o[4 * i + 3]);
                }
            }
        }
    }

    float4* op = (float4*)(O + base + ((size_t)p << 5));
    #pragma unroll
    for (int i = 0; i < 8; i++)
        op[i] = make_float4(o[4 * i], o[4 * i + 1], o[4 * i + 2], o[4 * i + 3]);
}

// ---------------------------------------------------------------------------
// BatchNorm over (B,H,W) per channel, fused +residual, z-batched.
// ---------------------------------------------------------------------------
__global__ void batchnorm_kernel(const float* __restrict__ X0, const float* __restrict__ X1,
                                 const float* __restrict__ g,
                                 const float* __restrict__ bt,
                                 const float* __restrict__ res0, const float* __restrict__ res1,
                                 float* __restrict__ Y0, float* __restrict__ Y1)
{
    const float* X   = blockIdx.y ? X1   : X0;
    const float* res = blockIdx.y ? res1 : res0;
    float*       Y   = blockIdx.y ? Y1   : Y0;

    int c = blockIdx.x;
    __shared__ float ssum[256], ssum2[256];
    float s = 0.0f, s2 = 0.0f;
    for (int b = 0; b < Bv; b++) {
        const float* xp = X + (((size_t)(b * Cv + c)) << 12);
        for (int p = threadIdx.x; p < HW; p += 256) {
            float v = xp[p];
            s += v; s2 += v * v;
        }
    }
    ssum[threadIdx.x] = s; ssum2[threadIdx.x] = s2;
    __syncthreads();
    for (int off = 128; off > 0; off >>= 1) {
        if (threadIdx.x < off) {
            ssum[threadIdx.x]  += ssum[threadIdx.x + off];
            ssum2[threadIdx.x] += ssum2[threadIdx.x + off];
        }
        __syncthreads();
    }
    float mu   = ssum[0] * (1.0f / (Bv * HW));
    float var  = ssum2[0] * (1.0f / (Bv * HW)) - mu * mu;
    float rstd = rsqrtf(var + 1e-5f);
    float gg = g[c], bb = bt[c];
    for (int b = 0; b < Bv; b++) {
        size_t off = ((size_t)(b * Cv + c)) << 12;
        for (int p = threadIdx.x; p < HW; p += 256)
            Y[off + p] = (X[off + p] - mu) * rstd * gg + bb + res[off + p];
    }
}

// ---------------------------------------------------------------------------
// Host-side orchestration
// ---------------------------------------------------------------------------
extern "C" void kernel_launch(void* const* d_in, const int* in_sizes, int n_in,
                              void* d_out, int out_size)
{
    const float* input1 = (const float*)d_in[0];
    const float* input2 = (const float*)d_in[1];
    const float* slf_g  = (const float*)d_in[6];
    const float* slf_b  = (const float*)d_in[7];
    const float* crs_g  = (const float*)d_in[12];
    const float* crs_b  = (const float*)d_in[13];
    const float* ffn_b1 = (const float*)d_in[15];
    const float* ffn_b2 = (const float*)d_in[17];
    const float* bn_g   = (const float*)d_in[18];
    const float* bn_b   = (const float*)d_in[19];

    cudaFuncSetAttribute(conv1x1_tc_kernel<false, false, true>,
                         cudaFuncAttributeMaxDynamicSharedMemorySize, SMEM_BYTES);
    cudaFuncSetAttribute(conv1x1_tc_kernel<true, true, false>,
                         cudaFuncAttributeMaxDynamicSharedMemorySize, SMEM_BYTES);
    cudaFuncSetAttribute(conv1x1_tc_kernel<false, true, false>,
                         cudaFuncAttributeMaxDynamicSharedMemorySize, SMEM_BYTES);
    cudaFuncSetAttribute(convln_kernel,
                         cudaFuncAttributeMaxDynamicSharedMemorySize, LSMEM_BYTES);

    float* buf = nullptr;
    cudaGetSymbolAddress((void**)&buf, g_scratch);
    float* Q1   = buf + 0u * NEL;   // Q1,K1,V1 consecutive (QKV segments)
    float* K1   = buf + 1u * NEL;
    float* V1   = buf + 2u * NEL;
    float* Q2   = buf + 3u * NEL;   // Q2,K2,V2 consecutive
    float* K2   = buf + 4u * NEL;
    float* V2   = buf + 5u * NEL;
    float* Ob1  = buf + 6u * NEL;
    float* Ob2  = buf + 7u * NEL;
    float* T1   = buf + 8u * NEL;
    float* T2   = buf + 9u * NEL;
    float* C1   = buf + 10u * NEL;
    float* C2   = buf + 11u * NEL;
    float* H1   = buf + 12u * NEL;
    float* H2   = buf + 13u * NEL;
    float* Tm1  = buf + 14u * NEL;
    float* Tm2  = buf + 15u * NEL;
    float* W8   = buf + 16u * NEL;  // pre-rounded weights

    WPtrs wp;
    wp.p[0] = (const float*)d_in[2];  // slf_wq
    wp.p[1] = (const float*)d_in[3];  // slf_wk
    wp.p[2] = (const float*)d_in[4];  // slf_wv
    wp.p[3] = (const float*)d_in[5];  // slf_fc
    wp.p[4] = (const float*)d_in[8];  // crs_wq
    wp.p[5] = (const float*)d_in[9];  // crs_wk
    wp.p[6] = (const float*)d_in[10]; // crs_wv
    wp.p[7] = (const float*)d_in[11]; // crs_fc
    wp.p[8] = (const float*)d_in[14]; // ffn_w1
    wp.p[9] = (const float*)d_in[16]; // ffn_w2
    round_weights_kernel<<<dim3(WELEM / 1024, NWMAT), 1024>>>(wp, W8);

    float* out1 = (float*)d_out;
    float* out2 = out1 + NEL;
    dim3 bb(256);

    // ---- slf phase ----
    // QKV: stacked slf wq|wk|wv (rows 0..767), pixel-major out -> Q,K,V segs.
    conv1x1_tc_kernel<false, false, true><<<dim3(64, 6, 2), bb, SMEM_BYTES>>>(
        input1, input2, nullptr, nullptr, W8, nullptr, Q1, Q2, nullptr, nullptr, 6);
    local_attn_kernel<<<dim3(512, 2), bb>>>(Q1, K1, V1, Ob1, Q2, K2, V2, Ob2);
    convln_kernel<<<dim3(128, 2), bb, LSMEM_BYTES>>>(
        Ob1, Ob2, W8 + 3u * WELEM, input1, input2, slf_g, slf_b, T1, T2);

    // ---- crs phase: merged Q (rows 0..255, X=T) + KV (rows 256..767, X=Tswap)
    conv1x1_tc_kernel<false, false, true><<<dim3(64, 6, 2), bb, SMEM_BYTES>>>(
        T1, T2, T2, T1, W8 + 4u * WELEM, nullptr, Q1, Q2, K1, K2, 2);
    local_attn_kernel<<<dim3(512, 2), bb>>>(Q1, K1, V1, Ob1, Q2, K2, V2, Ob2);
    convln_kernel<<<dim3(128, 2), bb, LSMEM_BYTES>>>(
        Ob1, Ob2, W8 + 7u * WELEM, T1, T2, crs_g, crs_b, C1, C2);

    // ---- ffn phase ----
    conv1x1_tc_kernel<true, true, false><<<dim3(64, 2, 2), bb, SMEM_BYTES>>>(
        C1, C2, nullptr, nullptr, W8 + 8u * WELEM, ffn_b1, H1, H2, nullptr, nullptr, 2);
    conv1x1_tc_kernel<false, true, false><<<dim3(64, 2, 2), bb, SMEM_BYTES>>>(
        H1, H2, nullptr, nullptr, W8 + 9u * WELEM, ffn_b2, Tm1, Tm2, nullptr, nullptr, 2);
    batchnorm_kernel<<<dim3(Cv, 2), bb>>>(
        Tm1, Tm2, bn_g, bn_b, C1, C2, out1, out2);
}

// round 13
// speedup vs baseline: 1.4613x; 1.4613x over previous
#include <cuda_runtime.h>
#include <cuda_bf16.h>
#include <cstdint>
#include <math.h>

// Problem constants
#define Bv   4
#define Cv   256
#define Hv   64
#define Wv   64
#define HW   4096          // Hv*Wv
#define NPIX 16384         // Bv*HW
#define NEL  4194304u      // Bv*Cv*HW
#define NHEAD 8
#define DHEAD 32
#define WELEM 65536        // 256*256 weight matrix elems
#define NWMAT 10

// Scratch: 16 fp32 tensors + pre-rounded weights (~271 MB).
__device__ float g_scratch[16u * NEL + NWMAT * WELEM];

// ---------------------------------------------------------------------------
// PTX helpers
// ---------------------------------------------------------------------------
__device__ __forceinline__ void cp_async16(void* smem_dst, const void* gsrc) {
    uint32_t s = (uint32_t)__cvta_generic_to_shared(smem_dst);
    asm volatile("cp.async.ca.shared.global [%0], [%1], 16;\n" :: "r"(s), "l"(gsrc));
}
__device__ __forceinline__ void cp_commit() {
    asm volatile("cp.async.commit_group;\n");
}
__device__ __forceinline__ void cp_wait0() {
    asm volatile("cp.async.wait_group 0;\n");
}
__device__ __forceinline__ uint32_t f2tf32(float x) {
    uint32_t y;
    asm("cvt.rna.tf32.f32 %0, %1;" : "=r"(y) : "f"(x));
    return y;
}
__device__ __forceinline__ void mma_tf32(float* d, const uint32_t* a, const uint32_t* b) {
    asm volatile(
        "mma.sync.aligned.m16n8k8.row.col.f32.tf32.tf32.f32 "
        "{%0,%1,%2,%3}, {%4,%5,%6,%7}, {%8,%9}, {%0,%1,%2,%3};\n"
        : "+f"(d[0]), "+f"(d[1]), "+f"(d[2]), "+f"(d[3])
        : "r"(a[0]), "r"(a[1]), "r"(a[2]), "r"(a[3]), "r"(b[0]), "r"(b[1]));
}

// ---------------------------------------------------------------------------
// Pre-round 10 weight matrices to tf32 (RNA) once.
// ---------------------------------------------------------------------------
struct WPtrs { const float* p[NWMAT]; };

__global__ void round_weights_kernel(WPtrs wp, float* __restrict__ dst) {
    int m = blockIdx.y;
    int i = blockIdx.x * blockDim.x + threadIdx.x;
    dst[m * WELEM + i] = __uint_as_float(f2tf32(wp.p[m][i]));
}

// ---------------------------------------------------------------------------
// conv1x1 as tf32 tensor-core GEMM, z-batched over two chains, y-split over
// two weight/input groups (primary rows [0, ysplit*128), secondary above).
// Channel-plane in and out. Stacked-M output segments (seg = row>>8).
// BM=128, BN=256, BK=32, 256 threads, warp tile 64x64.
// ---------------------------------------------------------------------------
#define BK     32
#define A_STR  36
#define B_STR  264
#define A_SZ   (128 * A_STR)
#define B_SZ   (BK * B_STR)
#define STG    (A_SZ + B_SZ)
#define SMEM_BYTES (2 * STG * 4)       // 104448 B

template<bool RELU, bool BIAS>
__global__ __launch_bounds__(256, 1)
void conv1x1_tc_kernel(const float* __restrict__ Xp0, const float* __restrict__ Xp1,
                       const float* __restrict__ Xs0, const float* __restrict__ Xs1,
                       const float* __restrict__ Wm,
                       const float* __restrict__ bias,
                       float* __restrict__ Yp0, float* __restrict__ Yp1,
                       float* __restrict__ Ys0, float* __restrict__ Ys1,
                       int ysplit)
{
    extern __shared__ float smem[];

    const bool sec = (int)blockIdx.y >= ysplit;
    const float* X = sec ? (blockIdx.z ? Xs1 : Xs0) : (blockIdx.z ? Xp1 : Xp0);
    float*       Y = sec ? (blockIdx.z ? Ys1 : Ys0) : (blockIdx.z ? Yp1 : Yp0);

    const int tb_n = blockIdx.x * 256;
    const int tb_m = blockIdx.y * 128;                  // row into stacked weights
    const int row0 = sec ? tb_m - ysplit * 128 : tb_m;  // row into output stack
    const int b    = tb_n >> 12;
    const int p0   = tb_n & 4095;

    const int t    = threadIdx.x;
    const int lane = t & 31;
    const int warp = t >> 5;
    const int wm0  = (warp >> 2) * 64;
    const int wn0  = (warp & 3) * 64;

    const float* Xbase = X + ((size_t)(b * Cv) << 12) + p0;

    float acc[4][8][4];
    #pragma unroll
    for (int i = 0; i < 4; i++)
        #pragma unroll
        for (int j = 0; j < 8; j++)
            #pragma unroll
            for (int r = 0; r < 4; r++) acc[i][j][r] = 0.0f;

    auto load_tile = [&](int kt, int s) {
        float* As = smem + s * STG;
        float* Bs = As + A_SZ;
        int k0 = kt * BK;
        #pragma unroll
        for (int i = 0; i < 4; i++) {
            int id = t + i * 256;
            int m  = id >> 3;
            int kq = id & 7;
            cp_async16(&As[m * A_STR + kq * 4],
                       Wm + (size_t)(tb_m + m) * Cv + k0 + kq * 4);
        }
        #pragma unroll
        for (int i = 0; i < 8; i++) {
            int id = t + i * 256;
            int kk = id >> 6;
            int nq = id & 63;
            cp_async16(&Bs[kk * B_STR + nq * 4],
                       Xbase + ((size_t)(k0 + kk) << 12) + nq * 4);
        }
        cp_commit();
    };

    load_tile(0, 0);

    const int a_r = lane >> 2;
    const int a_c = lane & 3;

    int buf = 0;
    const int KT = Cv / BK;
    for (int kt = 0; kt < KT; kt++) {
        cp_wait0();
        __syncthreads();
        if (kt + 1 < KT) load_tile(kt + 1, buf ^ 1);

        const float* As = smem + buf * STG;
        const float* Bs = As + A_SZ;

        #pragma unroll
        for (int ks = 0; ks < 4; ks++) {
            int kb = ks * 8;
            uint32_t afr[4][4], bfr[8][2];
            #pragma unroll
            for (int mi = 0; mi < 4; mi++) {
                const float* ap = As + (wm0 + mi * 16 + a_r) * A_STR + kb + a_c;
                afr[mi][0] = __float_as_uint(ap[0]);
                afr[mi][1] = __float_as_uint(ap[8 * A_STR]);
                afr[mi][2] = __float_as_uint(ap[4]);
                afr[mi][3] = __float_as_uint(ap[8 * A_STR + 4]);
            }
            #pragma unroll
            for (int ni = 0; ni < 8; ni++) {
                const float* bp = Bs + (kb + a_c) * B_STR + wn0 + ni * 8 + a_r;
                bfr[ni][0] = f2tf32(bp[0]);
                bfr[ni][1] = f2tf32(bp[4 * B_STR]);
            }
            #pragma unroll
            for (int mi = 0; mi < 4; mi++)
                #pragma unroll
                for (int ni = 0; ni < 8; ni++)
                    mma_tf32(acc[mi][ni], afr[mi], bfr[ni]);
        }
        __syncthreads();
        buf ^= 1;
    }

    #pragma unroll
    for (int mi = 0; mi < 4; mi++) {
        int rg  = row0 + wm0 + mi * 16 + a_r;
        int seg = rg >> 8;
        int ch  = rg & 255;
        float bv0 = BIAS ? bias[ch]     : 0.0f;
        float bv1 = BIAS ? bias[ch + 8] : 0.0f;
        float* Ys = Y + (size_t)seg * NEL;
        #pragma unroll
        for (int ni = 0; ni < 8; ni++) {
            int cb = p0 + wn0 + ni * 8 + 2 * a_c;
            size_t off0 = ((size_t)(b * Cv + ch) << 12) + cb;
            size_t off1 = off0 + ((size_t)8 << 12);
            float v0 = acc[mi][ni][0] + bv0;
            float v1 = acc[mi][ni][1] + bv0;
            float v2 = acc[mi][ni][2] + bv1;
            float v3 = acc[mi][ni][3] + bv1;
            if (RELU) {
                v0 = fmaxf(v0, 0.0f); v1 = fmaxf(v1, 0.0f);
                v2 = fmaxf(v2, 0.0f); v3 = fmaxf(v3, 0.0f);
            }
            *(float2*)(Ys + off0) = make_float2(v0, v1);
            *(float2*)(Ys + off1) = make_float2(v2, v3);
        }
    }
}

// ---------------------------------------------------------------------------
// Fused fc conv + residual + LayerNorm, z-batched.
// BM=256 (all channels), BN=64, BK=32, warp tile 64x32 (4m x 2n).
// Smem: 92KB (2 stages) -> 2 CTAs/SM (vs 1 at BN=128); grid (256, 2).
// ---------------------------------------------------------------------------
#define LA_STR 36
#define LB_STR 72
#define LA_SZ  (256 * LA_STR)          // 9216 floats
#define LB_SZ  (32 * LB_STR)           // 2304 floats
#define LSTG   (LA_SZ + LB_SZ)         // 11520 floats
#define S_STR  257
#define LSMEM_BYTES (2 * LSTG * 4)     // 92160 B >= 64*S_STR*4 = 65792 B

__global__ __launch_bounds__(256, 2)
void convln_kernel(const float* __restrict__ X0, const float* __restrict__ X1,
                   const float* __restrict__ Wm,
                   const float* __restrict__ res0, const float* __restrict__ res1,
                   const float* __restrict__ g,
                   const float* __restrict__ bt,
                   float* __restrict__ Y0, float* __restrict__ Y1)
{
    extern __shared__ float smem[];
    __shared__ float red[2][4][64];
    __shared__ float mus[64], rss[64];

    const float* X   = blockIdx.y ? X1   : X0;
    const float* res = blockIdx.y ? res1 : res0;
    float*       Y   = blockIdx.y ? Y1   : Y0;

    const int tb_n = blockIdx.x * 64;
    const int b    = tb_n >> 12;
    const int p0   = tb_n & 4095;

    const int t    = threadIdx.x;
    const int lane = t & 31;
    const int warp = t >> 5;
    const int wm0  = (warp >> 1) * 64;     // 4 m-rows of warps
    const int wn0  = (warp & 1) * 32;      // 2 n-cols of warps

    const float* Xbase = X + ((size_t)(b * Cv) << 12) + p0;

    float acc[4][4][4];
    #pragma unroll
    for (int i = 0; i < 4; i++)
        #pragma unroll
        for (int j = 0; j < 4; j++)
            #pragma unroll
            for (int r = 0; r < 4; r++) acc[i][j][r] = 0.0f;

    auto load_tile = [&](int kt, int s) {
        float* As = smem + s * LSTG;
        float* Bs = As + LA_SZ;
        int k0 = kt * BK;
        #pragma unroll
        for (int i = 0; i < 8; i++) {
            int id = t + i * 256;          // 0..2047
            int m  = id >> 3;              // 0..255
            int kq = id & 7;
            cp_async16(&As[m * LA_STR + kq * 4],
                       Wm + (size_t)m * Cv + k0 + kq * 4);
        }
        #pragma unroll
        for (int i = 0; i < 2; i++) {
            int id = t + i * 256;          // 0..511
            int kk = id >> 4;              // 0..31
            int nq = id & 15;              // 0..15 (64 px = 16 float4)
            cp_async16(&Bs[kk * LB_STR + nq * 4],
                       Xbase + ((size_t)(k0 + kk) << 12) + nq * 4);
        }
        cp_commit();
    };

    load_tile(0, 0);

    const int a_r = lane >> 2;
    const int a_c = lane & 3;

    int buf = 0;
    const int KT = Cv / BK;
    for (int kt = 0; kt < KT; kt++) {
        cp_wait0();
        __syncthreads();
        if (kt + 1 < KT) load_tile(kt + 1, buf ^ 1);

        const float* As = smem + buf * LSTG;
        const float* Bs = As + LA_SZ;

        #pragma unroll
        for (int ks = 0; ks < 4; ks++) {
            int kb = ks * 8;
            uint32_t afr[4][4], bfr[4][2];
            #pragma unroll
            for (int mi = 0; mi < 4; mi++) {
                const float* ap = As + (wm0 + mi * 16 + a_r) * LA_STR + kb + a_c;
                afr[mi][0] = __float_as_uint(ap[0]);
                afr[mi][1] = __float_as_uint(ap[8 * LA_STR]);
                afr[mi][2] = __float_as_uint(ap[4]);
                afr[mi][3] = __float_as_uint(ap[8 * LA_STR + 4]);
            }
            #pragma unroll
            for (int ni = 0; ni < 4; ni++) {
                const float* bp = Bs + (kb + a_c) * LB_STR + wn0 + ni * 8 + a_r;
                bfr[ni][0] = f2tf32(bp[0]);
                bfr[ni][1] = f2tf32(bp[4 * LB_STR]);
            }
            #pragma unroll
            for (int mi = 0; mi < 4; mi++)
                #pragma unroll
                for (int ni = 0; ni < 4; ni++)
                    mma_tf32(acc[mi][ni], afr[mi], bfr[ni]);
        }
        __syncthreads();
        buf ^= 1;
    }

    // Phase 1: fragments + residual -> S[pixel][channel]
    float* S = smem;                       // [64][S_STR]
    #pragma unroll
    for (int mi = 0; mi < 4; mi++) {
        int rbase = wm0 + mi * 16 + a_r;   // channel
        #pragma unroll
        for (int ni = 0; ni < 4; ni++) {
            int cbase = wn0 + ni * 8 + 2 * a_c;   // pixel within 64
            size_t off0 = ((size_t)(b * Cv + rbase) << 12) + p0 + cbase;
            size_t off1 = off0 + ((size_t)8 << 12);
            float2 r0 = *(const float2*)(res + off0);
            float2 r1 = *(const float2*)(res + off1);
            S[cbase * S_STR + rbase]           = acc[mi][ni][0] + r0.x;
            S[(cbase + 1) * S_STR + rbase]     = acc[mi][ni][1] + r0.y;
            S[cbase * S_STR + rbase + 8]       = acc[mi][ni][2] + r1.x;
            S[(cbase + 1) * S_STR + rbase + 8] = acc[mi][ni][3] + r1.y;
        }
    }
    __syncthreads();

    // Phase 2: per-pixel mean/var. thread t: pixel p=t&63, quarter q=t>>6.
    {
        int p = t & 63, q = t >> 6;
        float s = 0.0f, s2 = 0.0f;
        const float* row = S + p * S_STR + q * 64;
        #pragma unroll 8
        for (int j = 0; j < 64; j++) { float v = row[j]; s += v; s2 += v * v; }
        red[0][q][p] = s; red[1][q][p] = s2;
    }
    __syncthreads();
    if (t < 64) {
        float s  = red[0][0][t] + red[0][1][t] + red[0][2][t] + red[0][3][t];
        float s2 = red[1][0][t] + red[1][1][t] + red[1][2][t] + red[1][3][t];
        float mu  = s * (1.0f / Cv);
        float var = s2 * (1.0f / Cv) - mu * mu;
        mus[t] = mu;
        rss[t] = rsqrtf(var + 1e-6f);
    }
    __syncthreads();

    // Phase 3: normalize + write. thread t: pixel p=t&63, channels (t>>6)+4i.
    {
        int p = t & 63;
        float mu = mus[p], rstd = rss[p];
        int c0 = t >> 6;
        #pragma unroll 4
        for (int i = 0; i < 64; i++) {
            int c = c0 + 4 * i;
            float v = S[p * S_STR + c];
            Y[((size_t)(b * Cv + c) << 12) + p0 + p] =
                (v - mu) * rstd * g[c] + bt[c];
        }
    }
}

// ---------------------------------------------------------------------------
// Local 3x3 windowed attention, one thread per (b, head, pixel), z-batched.
// Channel-plane layout (R3/R10-proven).
// ---------------------------------------------------------------------------
__global__ void local_attn_kernel(const float* __restrict__ Q0, const float* __restrict__ K0,
                                  const float* __restrict__ V0, float* __restrict__ O0,
                                  const float* __restrict__ Q1, const float* __restrict__ K1,
                                  const float* __restrict__ V1, float* __restrict__ O1)
{
    const float* Q = blockIdx.y ? Q1 : Q0;
    const float* K = blockIdx.y ? K1 : K0;
    const float* V = blockIdx.y ? V1 : V0;
    float*       O = blockIdx.y ? O1 : O0;

    int n = blockIdx.x * blockDim.x + threadIdx.x;   // 0 .. 131071
    int p    = n & 4095;
    int x    = p & 63;
    int y    = p >> 6;
    int head = (n >> 12) & 7;
    int b    = n >> 15;

    size_t chbase = ((size_t)(b * Cv + head * DHEAD)) << 12;

    float q[DHEAD];
    #pragma unroll
    for (int d = 0; d < DHEAD; d++) q[d] = Q[chbase + ((size_t)d << 12) + p];

    const float scale = 0.17677669529663687f; // 1/sqrt(32)

    float logits[9];
    #pragma unroll
    for (int ki = 0; ki < 3; ki++) {
        #pragma unroll
        for (int kj = 0; kj < 3; kj++) {
            int yy = y + ki - 1, xx = x + kj - 1;
            float acc = 0.0f;
            if (yy >= 0 && yy < Hv && xx >= 0 && xx < Wv) {
                int pp = yy * Wv + xx;
                #pragma unroll
                for (int d = 0; d < DHEAD; d++)
                    acc = fmaf(q[d], K[chbase + ((size_t)d << 12) + pp], acc);
                acc *= scale;
            }
            logits[ki * 3 + kj] = acc;
        }
    }

    float m = logits[0];
    #pragma unroll
    for (int i = 1; i < 9; i++) m = fmaxf(m, logits[i]);
    float wgt[9]; float s = 0.0f;
    #pragma unroll
    for (int i = 0; i < 9; i++) { wgt[i] = __expf(logits[i] - m); s += wgt[i]; }
    float inv = 1.0f / s;
    #pragma unroll
    for (int i = 0; i < 9; i++) wgt[i] *= inv;

    #pragma unroll
    for (int d = 0; d < DHEAD; d++) {
        float acc = 0.0f;
        #pragma unroll
        for (int ki = 0; ki < 3; ki++) {
            #pragma unroll
            for (int kj = 0; kj < 3; kj++) {
                int yy = y + ki - 1, xx = x + kj - 1;
                if (yy >= 0 && yy < Hv && xx >= 0 && xx < Wv)
                    acc = fmaf(wgt[ki * 3 + kj],
                               V[chbase + ((size_t)d << 12) + yy * Wv + xx], acc);
            }
        }
        O[chbase + ((size_t)d << 12) + p] = acc;
    }
}

// ---------------------------------------------------------------------------
// BatchNorm over (B,H,W) per channel, fused +residual, z-batched.
// ---------------------------------------------------------------------------
__global__ void batchnorm_kernel(const float* __restrict__ X0, const float* __restrict__ X1,
                                 const float* __restrict__ g,
                                 const float* __restrict__ bt,
                                 const float* __restrict__ res0, const float* __restrict__ res1,
                                 float* __restrict__ Y0, float* __restrict__ Y1)
{
    const float* X   = blockIdx.y ? X1   : X0;
    const float* res = blockIdx.y ? res1 : res0;
    float*       Y   = blockIdx.y ? Y1   : Y0;

    int c = blockIdx.x;
    __shared__ float ssum[256], ssum2[256];
    float s = 0.0f, s2 = 0.0f;
    for (int b = 0; b < Bv; b++) {
        const float* xp = X + (((size_t)(b * Cv + c)) << 12);
        for (int p = threadIdx.x; p < HW; p += 256) {
            float v = xp[p];
            s += v; s2 += v * v;
        }
    }
    ssum[threadIdx.x] = s; ssum2[threadIdx.x] = s2;
    __syncthreads();
    for (int off = 128; off > 0; off >>= 1) {
        if (threadIdx.x < off) {
            ssum[threadIdx.x]  += ssum[threadIdx.x + off];
            ssum2[threadIdx.x] += ssum2[threadIdx.x + off];
        }
        __syncthreads();
    }
    float mu   = ssum[0] * (1.0f / (Bv * HW));
    float var  = ssum2[0] * (1.0f / (Bv * HW)) - mu * mu;
    float rstd = rsqrtf(var + 1e-5f);
    float gg = g[c], bb = bt[c];
    for (int b = 0; b < Bv; b++) {
        size_t off = ((size_t)(b * Cv + c)) << 12;
        for (int p = threadIdx.x; p < HW; p += 256)
            Y[off + p] = (X[off + p] - mu) * rstd * gg + bb + res[off + p];
    }
}

// ---------------------------------------------------------------------------
// Host-side orchestration
// ---------------------------------------------------------------------------
extern "C" void kernel_launch(void* const* d_in, const int* in_sizes, int n_in,
                              void* d_out, int out_size)
{
    const float* input1 = (const float*)d_in[0];
    const float* input2 = (const float*)d_in[1];
    const float* slf_g  = (const float*)d_in[6];
    const float* slf_b  = (const float*)d_in[7];
    const float* crs_g  = (const float*)d_in[12];
    const float* crs_b  = (const float*)d_in[13];
    const float* ffn_b1 = (const float*)d_in[15];
    const float* ffn_b2 = (const float*)d_in[17];
    const float* bn_g   = (const float*)d_in[18];
    const float* bn_b   = (const float*)d_in[19];

    cudaFuncSetAttribute(conv1x1_tc_kernel<false, false>,
                         cudaFuncAttributeMaxDynamicSharedMemorySize, SMEM_BYTES);
    cudaFuncSetAttribute(conv1x1_tc_kernel<true, true>,
                         cudaFuncAttributeMaxDynamicSharedMemorySize, SMEM_BYTES);
    cudaFuncSetAttribute(conv1x1_tc_kernel<false, true>,
                         cudaFuncAttributeMaxDynamicSharedMemorySize, SMEM_BYTES);
    cudaFuncSetAttribute(convln_kernel,
                         cudaFuncAttributeMaxDynamicSharedMemorySize, LSMEM_BYTES);

    float* buf = nullptr;
    cudaGetSymbolAddress((void**)&buf, g_scratch);
    float* Q1   = buf + 0u * NEL;   // Q1,K1,V1 consecutive (QKV segments)
    float* K1   = buf + 1u * NEL;
    float* V1   = buf + 2u * NEL;
    float* Q2   = buf + 3u * NEL;   // Q2,K2,V2 consecutive
    float* K2   = buf + 4u * NEL;
    float* V2   = buf + 5u * NEL;
    float* Ob1  = buf + 6u * NEL;
    float* Ob2  = buf + 7u * NEL;
    float* T1   = buf + 8u * NEL;
    float* T2   = buf + 9u * NEL;
    float* C1   = buf + 10u * NEL;
    float* C2   = buf + 11u * NEL;
    float* H1   = buf + 12u * NEL;
    float* H2   = buf + 13u * NEL;
    float* Tm1  = buf + 14u * NEL;
    float* Tm2  = buf + 15u * NEL;
    float* W8   = buf + 16u * NEL;  // pre-rounded weights

    WPtrs wp;
    wp.p[0] = (const float*)d_in[2];  // slf_wq
    wp.p[1] = (const float*)d_in[3];  // slf_wk
    wp.p[2] = (const float*)d_in[4];  // slf_wv
    wp.p[3] = (const float*)d_in[5];  // slf_fc
    wp.p[4] = (const float*)d_in[8];  // crs_wq
    wp.p[5] = (const float*)d_in[9];  // crs_wk
    wp.p[6] = (const float*)d_in[10]; // crs_wv
    wp.p[7] = (const float*)d_in[11]; // crs_fc
    wp.p[8] = (const float*)d_in[14]; // ffn_w1
    wp.p[9] = (const float*)d_in[16]; // ffn_w2
    round_weights_kernel<<<dim3(WELEM / 1024, NWMAT), 1024>>>(wp, W8);

    float* out1 = (float*)d_out;
    float* out2 = out1 + NEL;
    dim3 bb(256);

    // ---- slf phase ----
    // QKV: stacked slf wq|wk|wv (rows 0..767) -> Q,K,V segments.
    conv1x1_tc_kernel<false, false><<<dim3(64, 6, 2), bb, SMEM_BYTES>>>(
        input1, input2, nullptr, nullptr, W8, nullptr, Q1, Q2, nullptr, nullptr, 6);
    local_attn_kernel<<<dim3(512, 2), bb>>>(Q1, K1, V1, Ob1, Q2, K2, V2, Ob2);
    convln_kernel<<<dim3(256, 2), bb, LSMEM_BYTES>>>(
        Ob1, Ob2, W8 + 3u * WELEM, input1, input2, slf_g, slf_b, T1, T2);

    // ---- crs phase: merged Q (rows 0..255, X=T) + KV (rows 256..767, X=Tswap)
    conv1x1_tc_kernel<false, false><<<dim3(64, 6, 2), bb, SMEM_BYTES>>>(
        T1, T2, T2, T1, W8 + 4u * WELEM, nullptr, Q1, Q2, K1, K2, 2);
    local_attn_kernel<<<dim3(512, 2), bb>>>(Q1, K1, V1, Ob1, Q2, K2, V2, Ob2);
    convln_kernel<<<dim3(256, 2), bb, LSMEM_BYTES>>>(
        Ob1, Ob2, W8 + 7u * WELEM, T1, T2, crs_g, crs_b, C1, C2);

    // ---- ffn phase ----
    conv1x1_tc_kernel<true, true><<<dim3(64, 2, 2), bb, SMEM_BYTES>>>(
        C1, C2, nullptr, nullptr, W8 + 8u * WELEM, ffn_b1, H1, H2, nullptr, nullptr, 2);
    conv1x1_tc_kernel<false, true><<<dim3(64, 2, 2), bb, SMEM_BYTES>>>(
        H1, H2, nullptr, nullptr, W8 + 9u * WELEM, ffn_b2, Tm1, Tm2, nullptr, nullptr, 2);
    batchnorm_kernel<<<dim3(Cv, 2), bb>>>(
        Tm1, Tm2, bn_g, bn_b, C1, C2, out1, out2);
}